// round 9
// baseline (speedup 1.0000x reference)
#include <cuda_runtime.h>

// float32(3.4 * 3.4), exactly jnp.float32(RADIUS * RADIUS)
#define RADIUS2 11.559999465942383f
#define NSAMPLE 5
#define NBATCH  8
#define STAGE   64          // candidates staged in shared per block
#define TPB     256

// sq = (x0*x0 + x1*x1) + x2*x2, each op rounded once — bit-identical to the
// rel_err==0.0 passing versions.
__device__ __forceinline__ float sq3(float x0, float x1, float x2) {
    return __fadd_rn(__fadd_rn(__fmul_rn(x0, x0), __fmul_rn(x1, x1)),
                     __fmul_rn(x2, x2));
}

__device__ __forceinline__ float dist2(float qx, float qy, float qz, float sqq,
                                       float bx, float by, float bz, float sqk) {
    float dot = __fmaf_rn(qz, bz, __fmaf_rn(qy, by, __fmul_rn(qx, bx)));
    return __fsub_rn(__fadd_rn(sqq, sqk), __fmul_rn(2.0f, dot));
}

// Phase 1: one thread per row over STAGE staged candidates (branch-free mask).
// Phase 2: rows with <NSAMPLE hits in the stage are rescued cooperatively,
// one WARP per failed row (ballot scan, 32 candidates/iter, from k=0).
__global__ void ball_query_hybrid_kernel(const float* __restrict__ x,  // [B,N,3]
                                         float* __restrict__ out,      // [B,N,5]
                                         int n_rows, int npb)
{
    __shared__ float4 s_pts[STAGE];
    __shared__ int    s_fail[TPB];
    __shared__ int    s_nfail;

    int row0 = blockIdx.x * blockDim.x;
    int row  = row0 + threadIdx.x;
    int lane = threadIdx.x & 31;
    int wid  = threadIdx.x >> 5;
    int nwarps = blockDim.x >> 5;

    if (threadIdx.x == 0) s_nfail = 0;

    // Is this block entirely inside one batch, with a valid staged range?
    int last_row = min(row0 + (int)blockDim.x - 1, n_rows - 1);
    int b0 = row0 / npb;
    bool uniform = (b0 == last_row / npb) && (npb >= STAGE);

    if (uniform && threadIdx.x < STAGE) {
        const float* xb0 = x + (long long)b0 * npb * 3;
        int j = threadIdx.x;
        float bx = xb0[j * 3 + 0];
        float by = xb0[j * 3 + 1];
        float bz = xb0[j * 3 + 2];
        s_pts[j] = make_float4(bx, by, bz, sq3(bx, by, bz));
    }
    __syncthreads();

    // ---------- Phase 1: thread-per-row over the staged candidates ----------
    if (row < n_rows) {
        int b = row / npb;
        int q = row - b * npb;
        const float* xb = x + (long long)b * npb * 3;

        float qx = xb[q * 3 + 0];
        float qy = xb[q * 3 + 1];
        float qz = xb[q * 3 + 2];
        float sqq = sq3(qx, qy, qz);

        unsigned m0 = 0u, m1 = 0u;
        if (uniform) {
            #pragma unroll
            for (int j = 0; j < 32; j++) {
                float4 p = s_pts[j];
                float d2 = dist2(qx, qy, qz, sqq, p.x, p.y, p.z, p.w);
                m0 |= (d2 < RADIUS2) ? (1u << j) : 0u;
            }
            #pragma unroll
            for (int j = 0; j < 32; j++) {
                float4 p = s_pts[32 + j];
                float d2 = dist2(qx, qy, qz, sqq, p.x, p.y, p.z, p.w);
                m1 |= (d2 < RADIUS2) ? (1u << j) : 0u;
            }
        }
        unsigned long long mask = (unsigned long long)m0 |
                                  ((unsigned long long)m1 << 32);

        if (__popcll(mask) >= NSAMPLE) {
            unsigned long long t = mask;
            int i0 = __ffsll(t) - 1; t &= t - 1;
            int i1 = __ffsll(t) - 1; t &= t - 1;
            int i2 = __ffsll(t) - 1; t &= t - 1;
            int i3 = __ffsll(t) - 1; t &= t - 1;
            int i4 = __ffsll(t) - 1;
            float* o = out + (long long)row * NSAMPLE;
            o[0] = (float)i0; o[1] = (float)i1; o[2] = (float)i2;
            o[3] = (float)i3; o[4] = (float)i4;
        } else {
            int slot = atomicAdd(&s_nfail, 1);
            s_fail[slot] = row;
        }
    }
    __syncthreads();

    // ---------- Phase 2: warp-per-failed-row ballot rescue ----------
    int nf = s_nfail;
    for (int i = wid; i < nf; i += nwarps) {
        int frow = s_fail[i];
        int b = frow / npb;
        int q = frow - b * npb;
        const float* xb = x + (long long)b * npb * 3;

        float qx = xb[q * 3 + 0];
        float qy = xb[q * 3 + 1];
        float qz = xb[q * 3 + 2];
        float sqq = sq3(qx, qy, qz);

        int i0 = 0, i1 = 0, i2 = 0, i3 = 0, i4 = 0;
        int cnt = 0;

        int n_full = npb & ~31;
        const float* p = xb + lane * 3;

        for (int base = 0; base < n_full; base += 32, p += 96) {
            float bx = p[0];
            float by = p[1];
            float bz = p[2];
            float d2 = dist2(qx, qy, qz, sqq, bx, by, bz, sq3(bx, by, bz));
            unsigned m = __ballot_sync(0xffffffffu, d2 < RADIUS2);
            while (m && cnt < NSAMPLE) {
                int idx = base + __ffs(m) - 1;
                m &= m - 1;
                if (cnt == 0) {
                    i0 = idx; i1 = idx; i2 = idx; i3 = idx; i4 = idx;
                } else if (cnt == 1) {
                    i1 = idx;
                } else if (cnt == 2) {
                    i2 = idx;
                } else if (cnt == 3) {
                    i3 = idx;
                } else {
                    i4 = idx;
                }
                cnt++;
            }
            if (cnt == NSAMPLE) break;
        }

        if (cnt < NSAMPLE && n_full < npb) {
            int k = n_full + lane;
            bool pred = false;
            if (k < npb) {
                float bx = xb[k * 3 + 0];
                float by = xb[k * 3 + 1];
                float bz = xb[k * 3 + 2];
                float d2 = dist2(qx, qy, qz, sqq, bx, by, bz, sq3(bx, by, bz));
                pred = (d2 < RADIUS2);
            }
            unsigned m = __ballot_sync(0xffffffffu, pred);
            while (m && cnt < NSAMPLE) {
                int idx = n_full + __ffs(m) - 1;
                m &= m - 1;
                if (cnt == 0) {
                    i0 = idx; i1 = idx; i2 = idx; i3 = idx; i4 = idx;
                } else if (cnt == 1) {
                    i1 = idx;
                } else if (cnt == 2) {
                    i2 = idx;
                } else if (cnt == 3) {
                    i3 = idx;
                } else {
                    i4 = idx;
                }
                cnt++;
            }
        }

        if (lane == 0) {
            float* o = out + (long long)frow * NSAMPLE;
            o[0] = (float)i0; o[1] = (float)i1; o[2] = (float)i2;
            o[3] = (float)i3; o[4] = (float)i4;
        }
    }
}

extern "C" void kernel_launch(void* const* d_in, const int* in_sizes, int n_in,
                              void* d_out, int out_size) {
    const float* x = (const float*)d_in[0];
    float* out = (float*)d_out;

    int n_rows = out_size / NSAMPLE;       // B * N query rows
    int total_pts = in_sizes[0] / 3;       // B * N points
    int npb = total_pts / NBATCH;          // N per batch

    int blocks = (n_rows + TPB - 1) / TPB;
    ball_query_hybrid_kernel<<<blocks, TPB>>>(x, out, n_rows, npb);
}

// round 10
// speedup vs baseline: 1.0149x; 1.0149x over previous
#include <cuda_runtime.h>

// float32(3.4 * 3.4), exactly jnp.float32(RADIUS * RADIUS)
#define RADIUS2 11.559999465942383f
#define NSAMPLE 5
#define NBATCH  8
#define STAGE   64          // candidates staged in shared for phase 1
#define TPB     256
#define MAXW    128         // max mask words supported by block rescue (npb<=4096)

__device__ __forceinline__ float sq3(float x0, float x1, float x2) {
    return __fadd_rn(__fadd_rn(__fmul_rn(x0, x0), __fmul_rn(x1, x1)),
                     __fmul_rn(x2, x2));
}

__device__ __forceinline__ float dist2(float qx, float qy, float qz, float sqq,
                                       float bx, float by, float bz, float sqk) {
    float dot = __fmaf_rn(qz, bz, __fmaf_rn(qy, by, __fmul_rn(qx, bx)));
    return __fsub_rn(__fadd_rn(sqq, sqk), __fmul_rn(2.0f, dot));
}

// Phase 1: one thread per row over STAGE staged candidates (branch-free mask).
// Phase 2: each failed row is rescued by the WHOLE BLOCK: 8 warps compute the
// full per-chunk hit-mask array in parallel (no early-exit serialization),
// then warp 0 extracts the first NSAMPLE hits in ascending-k order.
__global__ void ball_query_hybrid2_kernel(const float* __restrict__ x,  // [B,N,3]
                                          float* __restrict__ out,      // [B,N,5]
                                          int n_rows, int npb)
{
    __shared__ float4   s_pts[STAGE];
    __shared__ int      s_fail[TPB];
    __shared__ int      s_nfail;
    __shared__ unsigned s_mask[MAXW];
    __shared__ int      s_slot[NSAMPLE];

    int row0 = blockIdx.x * blockDim.x;
    int row  = row0 + threadIdx.x;
    int lane = threadIdx.x & 31;
    int wid  = threadIdx.x >> 5;
    int nwarps = blockDim.x >> 5;

    if (threadIdx.x == 0) s_nfail = 0;

    int last_row = min(row0 + (int)blockDim.x - 1, n_rows - 1);
    int b0 = row0 / npb;
    bool uniform = (b0 == last_row / npb) && (npb >= STAGE);

    if (uniform && threadIdx.x < STAGE) {
        const float* xb0 = x + (long long)b0 * npb * 3;
        int j = threadIdx.x;
        float bx = xb0[j * 3 + 0];
        float by = xb0[j * 3 + 1];
        float bz = xb0[j * 3 + 2];
        s_pts[j] = make_float4(bx, by, bz, sq3(bx, by, bz));
    }
    __syncthreads();

    // ---------- Phase 1: thread-per-row over the staged candidates ----------
    if (row < n_rows) {
        int b = row / npb;
        int q = row - b * npb;
        const float* xb = x + (long long)b * npb * 3;

        float qx = xb[q * 3 + 0];
        float qy = xb[q * 3 + 1];
        float qz = xb[q * 3 + 2];
        float sqq = sq3(qx, qy, qz);

        unsigned m0 = 0u, m1 = 0u;
        if (uniform) {
            #pragma unroll
            for (int j = 0; j < 32; j++) {
                float4 p = s_pts[j];
                float d2 = dist2(qx, qy, qz, sqq, p.x, p.y, p.z, p.w);
                m0 |= (d2 < RADIUS2) ? (1u << j) : 0u;
            }
            #pragma unroll
            for (int j = 0; j < 32; j++) {
                float4 p = s_pts[32 + j];
                float d2 = dist2(qx, qy, qz, sqq, p.x, p.y, p.z, p.w);
                m1 |= (d2 < RADIUS2) ? (1u << j) : 0u;
            }
        }
        unsigned long long mask = (unsigned long long)m0 |
                                  ((unsigned long long)m1 << 32);

        if (__popcll(mask) >= NSAMPLE) {
            unsigned long long t = mask;
            int i0 = __ffsll(t) - 1; t &= t - 1;
            int i1 = __ffsll(t) - 1; t &= t - 1;
            int i2 = __ffsll(t) - 1; t &= t - 1;
            int i3 = __ffsll(t) - 1; t &= t - 1;
            int i4 = __ffsll(t) - 1;
            float* o = out + (long long)row * NSAMPLE;
            o[0] = (float)i0; o[1] = (float)i1; o[2] = (float)i2;
            o[3] = (float)i3; o[4] = (float)i4;
        } else {
            int slot = atomicAdd(&s_nfail, 1);
            s_fail[slot] = row;
        }
    }
    __syncthreads();

    // ---------- Phase 2: block-cooperative rescue, one failed row at a time --
    int nf = s_nfail;
    int nwords = (npb + 31) >> 5;

    if (nwords <= MAXW) {
        for (int i = 0; i < nf; i++) {
            int frow = s_fail[i];
            int b = frow / npb;
            int q = frow - b * npb;
            const float* xb = x + (long long)b * npb * 3;

            float qx = xb[q * 3 + 0];
            float qy = xb[q * 3 + 1];
            float qz = xb[q * 3 + 2];
            float sqq = sq3(qx, qy, qz);

            // All 8 warps fill the chunk-mask array in parallel.
            for (int chunk = wid; chunk < nwords; chunk += nwarps) {
                int k = chunk * 32 + lane;
                bool pred = false;
                if (k < npb) {
                    float bx = xb[k * 3 + 0];
                    float by = xb[k * 3 + 1];
                    float bz = xb[k * 3 + 2];
                    float d2 = dist2(qx, qy, qz, sqq, bx, by, bz,
                                     sq3(bx, by, bz));
                    pred = (d2 < RADIUS2);
                }
                unsigned m = __ballot_sync(0xffffffffu, pred);
                if (lane == 0) s_mask[chunk] = m;
            }
            __syncthreads();

            // Warp 0 extracts the first NSAMPLE hits in ascending-k order.
            if (wid == 0) {
                unsigned w[4];
                int local = 0;
                #pragma unroll
                for (int j = 0; j < 4; j++) {
                    int widx = lane * 4 + j;
                    w[j] = (widx < nwords) ? s_mask[widx] : 0u;
                    local += __popc(w[j]);
                }
                // Inclusive warp prefix-sum of per-lane hit counts.
                int incl = local;
                #pragma unroll
                for (int off = 1; off < 32; off <<= 1) {
                    int v = __shfl_up_sync(0xffffffffu, incl, off);
                    if (lane >= off) incl += v;
                }
                int excl  = incl - local;
                int total = __shfl_sync(0xffffffffu, incl, 31);

                // Each lane writes its hits whose global rank < NSAMPLE.
                int r = excl;
                #pragma unroll
                for (int j = 0; j < 4; j++) {
                    unsigned word = w[j];
                    int base = (lane * 4 + j) * 32;
                    while (word && r < NSAMPLE) {
                        int bit = __ffs(word) - 1;
                        word &= word - 1;
                        s_slot[r] = base + bit;
                        r++;
                    }
                }
                __syncwarp();

                if (lane == 0) {
                    int cnt = total < NSAMPLE ? total : NSAMPLE;
                    int first = (total > 0) ? s_slot[0] : 0;
                    float* o = out + (long long)frow * NSAMPLE;
                    #pragma unroll
                    for (int j = 0; j < NSAMPLE; j++)
                        o[j] = (float)((j < cnt) ? s_slot[j] : first);
                }
            }
            __syncthreads();   // s_mask/s_slot reuse for next failed row
        }
    } else {
        // Fallback (npb > 4096): warp-per-failed-row ballot scan.
        for (int i = wid; i < nf; i += nwarps) {
            int frow = s_fail[i];
            int b = frow / npb;
            int q = frow - b * npb;
            const float* xb = x + (long long)b * npb * 3;

            float qx = xb[q * 3 + 0];
            float qy = xb[q * 3 + 1];
            float qz = xb[q * 3 + 2];
            float sqq = sq3(qx, qy, qz);

            int i0 = 0, i1 = 0, i2 = 0, i3 = 0, i4 = 0;
            int cnt = 0;
            for (int base = 0; base < npb; base += 32) {
                int k = base + lane;
                bool pred = false;
                if (k < npb) {
                    float bx = xb[k * 3 + 0];
                    float by = xb[k * 3 + 1];
                    float bz = xb[k * 3 + 2];
                    float d2 = dist2(qx, qy, qz, sqq, bx, by, bz,
                                     sq3(bx, by, bz));
                    pred = (d2 < RADIUS2);
                }
                unsigned m = __ballot_sync(0xffffffffu, pred);
                while (m && cnt < NSAMPLE) {
                    int idx = base + __ffs(m) - 1;
                    m &= m - 1;
                    if (cnt == 0) {
                        i0 = idx; i1 = idx; i2 = idx; i3 = idx; i4 = idx;
                    } else if (cnt == 1) { i1 = idx;
                    } else if (cnt == 2) { i2 = idx;
                    } else if (cnt == 3) { i3 = idx;
                    } else               { i4 = idx; }
                    cnt++;
                }
                if (cnt == NSAMPLE) break;
            }
            if (lane == 0) {
                float* o = out + (long long)frow * NSAMPLE;
                o[0] = (float)i0; o[1] = (float)i1; o[2] = (float)i2;
                o[3] = (float)i3; o[4] = (float)i4;
            }
        }
    }
}

extern "C" void kernel_launch(void* const* d_in, const int* in_sizes, int n_in,
                              void* d_out, int out_size) {
    const float* x = (const float*)d_in[0];
    float* out = (float*)d_out;

    int n_rows = out_size / NSAMPLE;       // B * N query rows
    int total_pts = in_sizes[0] / 3;       // B * N points
    int npb = total_pts / NBATCH;          // N per batch

    int blocks = (n_rows + TPB - 1) / TPB;
    ball_query_hybrid2_kernel<<<blocks, TPB>>>(x, out, n_rows, npb);
}

// round 11
// speedup vs baseline: 1.2593x; 1.2407x over previous
#include <cuda_runtime.h>

// float32(3.4 * 3.4), exactly jnp.float32(RADIUS * RADIUS)
#define RADIUS2 11.559999465942383f
#define NSAMPLE 5
#define NBATCH  8
#define STAGE   64          // candidates staged in shared for phase 1
#define TPB     256
#define ROWS_PER_BLOCK (TPB / 2)

__device__ __forceinline__ float sq3(float x0, float x1, float x2) {
    return __fadd_rn(__fadd_rn(__fmul_rn(x0, x0), __fmul_rn(x1, x1)),
                     __fmul_rn(x2, x2));
}

__device__ __forceinline__ float dist2(float qx, float qy, float qz, float sqq,
                                       float bx, float by, float bz, float sqk) {
    float dot = __fmaf_rn(qz, bz, __fmaf_rn(qy, by, __fmul_rn(qx, bx)));
    return __fsub_rn(__fadd_rn(sqq, sqk), __fmul_rn(2.0f, dot));
}

// Phase 1: TWO threads per row (adjacent lanes). Each evaluates 32 of the 64
// staged candidates into a 32-bit mask; shfl_xor(1) merges the pair on the
// even lane, which extracts the first NSAMPLE hits (ascending k).
// Phase 2: rows with <NSAMPLE staged hits are rescued warp-per-row with an
// early-exiting ballot scan from k=0 (re-derives everything, no carry state).
__global__ void __launch_bounds__(TPB)
ball_query_pair_kernel(const float* __restrict__ x,  // [B,N,3]
                       float* __restrict__ out,      // [B,N,5]
                       int n_rows, int npb)
{
    __shared__ float4 s_pts[STAGE];
    __shared__ int    s_fail[ROWS_PER_BLOCK];
    __shared__ int    s_nfail;

    int row0  = blockIdx.x * ROWS_PER_BLOCK;
    int half  = threadIdx.x & 1;                 // which 32 candidates
    int row   = row0 + (threadIdx.x >> 1);
    int lane  = threadIdx.x & 31;
    int wid   = threadIdx.x >> 5;
    int nwarps = TPB >> 5;

    if (threadIdx.x == 0) s_nfail = 0;

    // Block-uniform batch check (all rows of the block in one batch, staged
    // range valid).
    int last_row = min(row0 + ROWS_PER_BLOCK - 1, n_rows - 1);
    int b0 = row0 / npb;
    bool uniform = (b0 == last_row / npb) && (npb >= STAGE);

    if (uniform && threadIdx.x < STAGE) {
        const float* xb0 = x + (long long)b0 * npb * 3;
        int j = threadIdx.x;
        float bx = xb0[j * 3 + 0];
        float by = xb0[j * 3 + 1];
        float bz = xb0[j * 3 + 2];
        s_pts[j] = make_float4(bx, by, bz, sq3(bx, by, bz));
    }
    __syncthreads();

    // ---------- Phase 1 ----------
    {
        int rr = min(row, n_rows - 1);           // clamp; real guard at output
        // uniform => batch is b0, no per-thread division needed.
        int q = rr - b0 * npb;
        const float* xb = x + (long long)b0 * npb * 3;

        unsigned m = 0u;
        float qx = 0.f, qy = 0.f, qz = 0.f, sqq = 0.f;
        if (uniform) {
            qx = xb[q * 3 + 0];
            qy = xb[q * 3 + 1];
            qz = xb[q * 3 + 2];
            sqq = sq3(qx, qy, qz);
            int j0 = half * 32;
            #pragma unroll
            for (int j = 0; j < 32; j++) {
                float4 p = s_pts[j0 + j];
                float d2 = dist2(qx, qy, qz, sqq, p.x, p.y, p.z, p.w);
                m |= (d2 < RADIUS2) ? (1u << j) : 0u;
            }
        }

        // Merge pair masks: even lane gets partner's (upper-32) mask.
        unsigned other = __shfl_xor_sync(0xffffffffu, m, 1);

        if (half == 0 && row < n_rows) {
            unsigned long long mask = (unsigned long long)m |
                                      ((unsigned long long)other << 32);
            if (__popcll(mask) >= NSAMPLE) {
                unsigned long long t = mask;
                int i0 = __ffsll(t) - 1; t &= t - 1;
                int i1 = __ffsll(t) - 1; t &= t - 1;
                int i2 = __ffsll(t) - 1; t &= t - 1;
                int i3 = __ffsll(t) - 1; t &= t - 1;
                int i4 = __ffsll(t) - 1;
                float* o = out + (long long)row * NSAMPLE;
                o[0] = (float)i0; o[1] = (float)i1; o[2] = (float)i2;
                o[3] = (float)i3; o[4] = (float)i4;
            } else {
                int slot = atomicAdd(&s_nfail, 1);
                s_fail[slot] = row;
            }
        }
    }
    __syncthreads();

    // ---------- Phase 2: warp-per-failed-row, early-exit ballot scan --------
    int nf = s_nfail;
    for (int i = wid; i < nf; i += nwarps) {
        int frow = s_fail[i];
        int b = frow / npb;                      // rare path: division OK
        int q = frow - b * npb;
        const float* xb = x + (long long)b * npb * 3;

        float qx = xb[q * 3 + 0];
        float qy = xb[q * 3 + 1];
        float qz = xb[q * 3 + 2];
        float sqq = sq3(qx, qy, qz);

        int i0 = 0, i1 = 0, i2 = 0, i3 = 0, i4 = 0;
        int cnt = 0;

        for (int base = 0; base < npb; base += 32) {
            int k = base + lane;
            bool pred = false;
            if (k < npb) {
                float bx = xb[k * 3 + 0];
                float by = xb[k * 3 + 1];
                float bz = xb[k * 3 + 2];
                float d2 = dist2(qx, qy, qz, sqq, bx, by, bz, sq3(bx, by, bz));
                pred = (d2 < RADIUS2);
            }
            unsigned mm = __ballot_sync(0xffffffffu, pred);
            while (mm && cnt < NSAMPLE) {
                int idx = base + __ffs(mm) - 1;
                mm &= mm - 1;
                if (cnt == 0) {
                    i0 = idx; i1 = idx; i2 = idx; i3 = idx; i4 = idx;
                } else if (cnt == 1) { i1 = idx;
                } else if (cnt == 2) { i2 = idx;
                } else if (cnt == 3) { i3 = idx;
                } else               { i4 = idx; }
                cnt++;
            }
            if (cnt == NSAMPLE) break;
        }

        if (lane == 0) {
            float* o = out + (long long)frow * NSAMPLE;
            o[0] = (float)i0; o[1] = (float)i1; o[2] = (float)i2;
            o[3] = (float)i3; o[4] = (float)i4;
        }
    }
}

extern "C" void kernel_launch(void* const* d_in, const int* in_sizes, int n_in,
                              void* d_out, int out_size) {
    const float* x = (const float*)d_in[0];
    float* out = (float*)d_out;

    int n_rows = out_size / NSAMPLE;       // B * N query rows
    int total_pts = in_sizes[0] / 3;       // B * N points
    int npb = total_pts / NBATCH;          // N per batch

    int blocks = (n_rows + ROWS_PER_BLOCK - 1) / ROWS_PER_BLOCK;
    ball_query_pair_kernel<<<blocks, TPB>>>(x, out, n_rows, npb);
}